// round 14
// baseline (speedup 1.0000x reference)
#include <cuda_runtime.h>

#define B_    128
#define T_    4096
#define FEAT_ 64
#define HID_  24
#define G3_   72            // 3 * HID
#define SPT   4             // steps per tick
#define NTB   (T_ / SPT)    // 1024 compute ticks for warp 0
#define NTICK (NTB + 3)     // + pipeline drain

// Scratch for precomputed GRU1 input gates: [B, T, 72]  (~151 MB)
__device__ float g_xg1[(size_t)B_ * T_ * G3_];

// sigmoid(a) = 0.5 + 0.5*tanh(a/2): r,z weights/biases/x pre-scaled by 0.5.
#define HFC 0.5f

typedef unsigned long long u64;

// ---------------------------------------------------------------------------
// Packed f32x2 helpers (PTX 8.6, sm_100+)
// ---------------------------------------------------------------------------
#define FMA2(acc, a, b) \
    asm("fma.rn.f32x2 %0, %1, %2, %0;" : "+l"(acc) : "l"(a), "l"(b))
#define ADD2(d, a, b) \
    asm("add.rn.f32x2 %0, %1, %2;" : "=l"(d) : "l"(a), "l"(b))
#define MUL2(d, a, b) \
    asm("mul.rn.f32x2 %0, %1, %2;" : "=l"(d) : "l"(a), "l"(b))
#define BAR_SYNC(id, cnt) \
    asm volatile("bar.sync %0, %1;" :: "r"(id), "r"(cnt) : "memory")

__device__ __forceinline__ u64 pk2(float lo, float hi) {
    u64 r;
    asm("mov.b64 %0, {%1, %2};" : "=l"(r) : "f"(lo), "f"(hi));
    return r;
}
__device__ __forceinline__ float hsum2(u64 v) {
    float lo, hi;
    asm("mov.b64 {%0, %1}, %2;" : "=f"(lo), "=f"(hi) : "l"(v));
    return lo + hi;
}
__device__ __forceinline__ float tanha(float x) {
    float r;
    asm("tanh.approx.f32 %0, %1;" : "=f"(r) : "f"(x));
    return r;
}
__device__ __forceinline__ void load_h64(u64 h64[12], const float* buf) {
    const ulonglong2* hp = (const ulonglong2*)buf;
    #pragma unroll
    for (int q = 0; q < 6; q++) { ulonglong2 v = hp[q]; h64[2*q] = v.x; h64[2*q+1] = v.y; }
}

// one GRU step: register h, shuffle-gathered pairs, MUFU-tanh gates.
__device__ __forceinline__ float gru_step_sh(float h,
    float xr_s, float xz_s, float xn,
    const u64* wr, const u64* wz, const u64* wn,
    float bhr_s, float bhz_s, float bhn)
{
    u64 h64[12];
    #pragma unroll
    for (int j = 0; j < 12; j++) {
        float lo = __shfl_sync(0xffffffffu, h, 2*j);
        float hi = __shfl_sync(0xffffffffu, h, 2*j+1);
        h64[j] = pk2(lo, hi);
    }
    u64 ar0 = pk2(xr_s, bhr_s), ar1 = 0ull;
    u64 az0 = pk2(xz_s, bhz_s), az1 = 0ull;
    u64 an0 = pk2(bhn, 0.f),    an1 = 0ull;
    #pragma unroll
    for (int j = 0; j < 6; j++) {
        FMA2(ar0, wr[j],     h64[j]);
        FMA2(ar1, wr[j + 6], h64[j + 6]);
        FMA2(an0, wn[j],     h64[j]);
        FMA2(an1, wn[j + 6], h64[j + 6]);
        FMA2(az0, wz[j],     h64[j]);
        FMA2(az1, wz[j + 6], h64[j + 6]);
    }
    ADD2(ar0, ar0, ar1);
    ADD2(an0, an0, an1);
    ADD2(az0, az0, az1);
    float r = fmaf(HFC, tanha(hsum2(ar0)), HFC);
    float n = tanha(fmaf(r, hsum2(an0), xn));
    float z = fmaf(HFC, tanha(hsum2(az0)), HFC);
    return fmaf(z, h - n, n);
}

// ---------------------------------------------------------------------------
// FUSED kernel: one CTA per batch, 8 warps.
//   warps 0-3 (consumer): layer-pipelined GRU stack, named barrier 2.
//     warp 0: GRU1 (register h, shuffle)     warp 2: GRU2
//     warp 1: xg2 steps 0-1 + FC+conf 0-1 + xg1 stager
//     warp 3: xg2 steps 2-3 + FC+conf 2-3
//   warps 4-7 (producer): conv+LN+xg1 GEMM for THIS batch, 32 passes of 128
//     timesteps, named barrier 1; posts smem progress counter after each pass.
//   confidence is computed in-register by the FC warps (no separate kernel,
//   no 128MB DRAM round trip).
// ---------------------------------------------------------------------------
__global__ void __launch_bounds__(256, 1) fused_kernel(
    const float* __restrict__ x,
    const float* __restrict__ h1_0, const float* __restrict__ h2_0,
    const float* __restrict__ conv_w, const float* __restrict__ conv_b,
    const float* __restrict__ gamma,  const float* __restrict__ beta,
    const float* __restrict__ w_ih1,  const float* __restrict__ b_ih1,
    const float* __restrict__ w_hh1, const float* __restrict__ b_hh1,
    const float* __restrict__ w_ih2, const float* __restrict__ w_hh2,
    const float* __restrict__ b_ih2, const float* __restrict__ b_hh2,
    const float* __restrict__ fc_w,  const float* __restrict__ fc_b,
    float* __restrict__ out_noise, float* __restrict__ out_h1,
    float* __restrict__ out_h2, float* __restrict__ out_conf,
    int write_extra)
{
    // ---- producer dynamic smem ----
    extern __shared__ float psm[];
    float* xs  = psm;                // 130*68 = 8840
    float* cwt = xs + 130 * 68;      // 3072 (transposed [f][k][c])
    float* cb  = cwt + 3072;         // 64
    float* gm  = cb + 64;            // 64
    float* bt  = gm + 64;            // 64
    float* wi  = bt + 64;            // 4608
    float* b1  = wi + 4608;          // 72

    // ---- consumer static smem ----
    __shared__ __align__(16) float h1pub[2][SPT][24];
    __shared__ __align__(16) float h2pub[2][SPT][24];
    __shared__ __align__(16) float xg2buf[2][SPT][72];
    __shared__ __align__(16) float xgbuf[2][SPT][72];
    __shared__ int prog;

    const int b    = blockIdx.x;
    const int tid  = threadIdx.x;
    const int w    = tid >> 5;
    const int lane = tid & 31;

    if (tid == 0) prog = 0;
    __syncthreads();

    if (w >= 4) {
        // ================= PRODUCER (warps 4-7) =================
        const int ptid = tid - 128;
        for (int i = ptid; i < 3072; i += 128) {
            int f = i / 48, r = i % 48, k = r >> 4, c = r & 15;
            cwt[i] = conv_w[f * 48 + c * 3 + k];
        }
        for (int i = ptid; i < 4608; i += 128) wi[i] = w_ih1[i];
        if (ptid < 64) { cb[ptid] = conv_b[ptid]; gm[ptid] = gamma[ptid]; bt[ptid] = beta[ptid]; }
        if (ptid < 72) b1[ptid] = b_ih1[ptid];

        const float* xb = x + (size_t)b * T_ * FEAT_;
        for (int pass = 0; pass < T_ / 128; pass++) {
            const int t0 = pass << 7;
            for (int i = ptid; i < 130 * 64; i += 128) {
                int r = i >> 6, f = i & 63;
                int t = t0 - 2 + r;
                xs[r * 68 + f] = (t >= 0) ? xb[(size_t)t * 64 + f] : 0.f;
            }
            BAR_SYNC(1, 128);

            float y[64];
            #pragma unroll
            for (int g = 0; g < 4; g++) {
                u64 xk2[3][8];
                #pragma unroll
                for (int k = 0; k < 3; k++) {
                    const float4* p = (const float4*)&xs[(ptid + k) * 68 + g * 16];
                    #pragma unroll
                    for (int q = 0; q < 4; q++) {
                        float4 v = p[q];
                        xk2[k][2*q]   = pk2(v.x, v.y);
                        xk2[k][2*q+1] = pk2(v.z, v.w);
                    }
                }
                #pragma unroll
                for (int fo = 0; fo < 16; fo++) {
                    const int f = g * 16 + fo;
                    u64 a0 = 0ull, a1 = 0ull;
                    const ulonglong2* wp = (const ulonglong2*)&cwt[f * 48];
                    #pragma unroll
                    for (int k = 0; k < 3; k++) {
                        #pragma unroll
                        for (int q = 0; q < 4; q++) {
                            ulonglong2 wv = wp[k * 4 + q];
                            FMA2(a0, wv.x, xk2[k][2*q]);
                            FMA2(a1, wv.y, xk2[k][2*q+1]);
                        }
                    }
                    ADD2(a0, a0, a1);
                    y[f] = hsum2(a0) + cb[f];
                }
            }

            float s = 0.f, s2 = 0.f;
            #pragma unroll
            for (int f = 0; f < 64; f++) { s += y[f]; s2 = fmaf(y[f], y[f], s2); }
            float mean = s * (1.f / 64.f);
            float var  = s2 * (1.f / 64.f) - mean * mean;
            float rs   = rsqrtf(var + 1e-5f);
            #pragma unroll
            for (int f = 0; f < 64; f++) y[f] = (y[f] - mean) * rs * gm[f] + bt[f];

            u64 y2[32];
            #pragma unroll
            for (int j = 0; j < 32; j++) y2[j] = pk2(y[2*j], y[2*j+1]);

            float* outp = g_xg1 + ((size_t)b * T_ + (t0 + ptid)) * G3_;
            for (int o4 = 0; o4 < 18; o4++) {
                const int o = o4 * 4;
                u64 a0 = 0ull, a1 = 0ull, e0 = 0ull, e1 = 0ull;
                u64 c0 = 0ull, c1 = 0ull, d0 = 0ull, d1 = 0ull;
                const ulonglong2* w0 = (const ulonglong2*)&wi[(o + 0) * 64];
                const ulonglong2* w1 = (const ulonglong2*)&wi[(o + 1) * 64];
                const ulonglong2* w2 = (const ulonglong2*)&wi[(o + 2) * 64];
                const ulonglong2* w3 = (const ulonglong2*)&wi[(o + 3) * 64];
                #pragma unroll
                for (int c = 0; c < 16; c++) {
                    ulonglong2 v0 = w0[c], v1 = w1[c], v2 = w2[c], v3 = w3[c];
                    FMA2(a0, v0.x, y2[2*c]); FMA2(a1, v0.y, y2[2*c+1]);
                    FMA2(e0, v1.x, y2[2*c]); FMA2(e1, v1.y, y2[2*c+1]);
                    FMA2(c0, v2.x, y2[2*c]); FMA2(d0, v3.x, y2[2*c]);
                    FMA2(c1, v2.y, y2[2*c+1]); FMA2(d1, v3.y, y2[2*c+1]);
                }
                ADD2(a0, a0, a1); ADD2(e0, e0, e1); ADD2(c0, c0, c1); ADD2(d0, d0, d1);
                float4 res;
                res.x = hsum2(a0) + b1[o + 0];
                res.y = hsum2(e0) + b1[o + 1];
                res.z = hsum2(c0) + b1[o + 2];
                res.w = hsum2(d0) + b1[o + 3];
                ((float4*)outp)[o4] = res;
            }

            __threadfence_block();
            BAR_SYNC(1, 128);
            if (ptid == 0) *(volatile int*)&prog = (pass + 1) * 128;
        }
        return;
    }

    // ================= CONSUMER (warps 0-3) =================
    const int ln = (lane < 24) ? lane : (lane - 8);

    u64 wr[12], wz[12], wn[12], wf[12];
    float bhr = 0.f, bhz = 0.f, bhn = 0.f, bf = 0.f;
    {
        const u64 sH = pk2(HFC, HFC);
        const float* W  = (w == 0) ? w_hh1 : (w == 2) ? w_hh2 : w_ih2;
        const float* Bv = (w == 0) ? b_hh1 : (w == 2) ? b_hh2 : b_ih2;
        const u64* Wr = (const u64*)(W + ln * 24);
        const u64* Wz = (const u64*)(W + (24 + ln) * 24);
        const u64* Wn = (const u64*)(W + (48 + ln) * 24);
        #pragma unroll
        for (int j = 0; j < 12; j++) {
            u64 a = Wr[j], c = Wz[j];
            MUL2(wr[j], a, sH);
            MUL2(wz[j], c, sH);
            wn[j] = Wn[j];
        }
        bhr = HFC * Bv[ln]; bhz = HFC * Bv[24 + ln]; bhn = Bv[48 + ln];
        if (w == 1 || w == 3) {
            const u64* Wf = (const u64*)(fc_w + lane * 24);
            #pragma unroll
            for (int j = 0; j < 12; j++) wf[j] = Wf[j];
            bf = fc_b[lane];
        }
    }

    float hreg = 0.f;
    if (w == 0 && lane < 24) hreg = h1_0[b * 24 + lane];
    if (w == 2 && lane < 24) hreg = h2_0[b * 24 + lane];

    float* xgp = g_xg1 + (size_t)b * T_ * G3_;

    while (*(volatile int*)&prog < 8) __nanosleep(200);
    __threadfence_block();
    for (int i = tid; i < SPT * 72; i += 128) {
        int g = (i % 72) / 24;
        float sc = (g == 2) ? 1.f : HFC;
        ((float*)xgbuf[0])[i] = sc * xgp[i];
    }
    float rx[SPT], rz_[SPT], rn_[SPT];
    if (w == 1 && lane < 24) {
        #pragma unroll
        for (int s = 0; s < SPT; s++) {
            rx[s]  = xgp[(size_t)(SPT + s) * 72 + lane];
            rz_[s] = xgp[(size_t)(SPT + s) * 72 + 24 + lane];
            rn_[s] = xgp[(size_t)(SPT + s) * 72 + 48 + lane];
        }
    }
    BAR_SYNC(2, 128);

    for (int tau = 0; tau < NTICK; tau++) {
        const int ws = tau & 1, rs = ws ^ 1;
        if (w == 0) {
            if (tau < NTB) {
                float xr[SPT], xz[SPT], xn[SPT], hs[SPT];
                #pragma unroll
                for (int s = 0; s < SPT; s++) {
                    xr[s] = xgbuf[ws][s][ln];
                    xz[s] = xgbuf[ws][s][24 + ln];
                    xn[s] = xgbuf[ws][s][48 + ln];
                }
                #pragma unroll
                for (int s = 0; s < SPT; s++) {
                    hreg = gru_step_sh(hreg, xr[s], xz[s], xn[s],
                                       wr, wz, wn, bhr, bhz, bhn);
                    hs[s] = hreg;
                }
                if (lane < 24) {
                    #pragma unroll
                    for (int s = 0; s < SPT; s++) h1pub[ws][s][lane] = hs[s];
                }
            }
        } else if (w == 2) {
            if (tau >= 2 && tau <= NTB + 1) {
                float xr[SPT], xz[SPT], xn[SPT], hs[SPT];
                #pragma unroll
                for (int s = 0; s < SPT; s++) {
                    xr[s] = xg2buf[rs][s][ln];
                    xz[s] = xg2buf[rs][s][24 + ln];
                    xn[s] = xg2buf[rs][s][48 + ln];
                }
                #pragma unroll
                for (int s = 0; s < SPT; s++) {
                    hreg = gru_step_sh(hreg, xr[s], xz[s], xn[s],
                                       wr, wz, wn, bhr, bhz, bhn);
                    hs[s] = hreg;
                }
                if (lane < 24) {
                    #pragma unroll
                    for (int s = 0; s < SPT; s++) h2pub[ws][s][lane] = hs[s];
                }
            }
        } else {
            const int s0 = (w == 1) ? 0 : 2;
            if (tau >= 1 && tau <= NTB) {
                #pragma unroll
                for (int sel = 0; sel < 2; sel++) {
                    const int s = s0 + sel;
                    u64 h64[12];
                    load_h64(h64, h1pub[rs][s]);
                    u64 ar = pk2(bhr, 0.f);
                    u64 az = pk2(bhz, 0.f);
                    u64 an = pk2(bhn, 0.f);
                    #pragma unroll
                    for (int j = 0; j < 12; j++) {
                        FMA2(ar, wr[j], h64[j]); FMA2(az, wz[j], h64[j]); FMA2(an, wn[j], h64[j]);
                    }
                    if (lane < 24) {
                        xg2buf[ws][s][lane]      = hsum2(ar);
                        xg2buf[ws][s][24 + lane] = hsum2(az);
                        xg2buf[ws][s][48 + lane] = hsum2(an);
                    }
                }
            }
            if (tau >= 3) {
                const size_t t0o = (size_t)b * T_ + SPT * (tau - 3);
                #pragma unroll
                for (int sel = 0; sel < 2; sel++) {
                    const int s = s0 + sel;
                    u64 h64[12];
                    load_h64(h64, h2pub[rs][s]);
                    u64 a = pk2(bf, 0.f);
                    #pragma unroll
                    for (int j = 0; j < 12; j++) FMA2(a, wf[j], h64[j]);
                    float o = hsum2(a);
                    out_noise[(t0o + s) * 32 + lane] = o;
                    if (write_extra) {
                        // confidence: std over the 32 FC outputs (ddof=1)
                        float su = o, sq = o * o;
                        #pragma unroll
                        for (int m = 16; m >= 1; m >>= 1) {
                            su += __shfl_xor_sync(0xffffffffu, su, m);
                            sq += __shfl_xor_sync(0xffffffffu, sq, m);
                        }
                        if (lane == 0) {
                            float ss = fmaxf(sq - su * su * (1.f / 32.f), 0.f);
                            float sd = sqrtf(ss * (1.f / 31.f));
                            out_conf[t0o + s] = __fdividef(1.f, 1.f + sd);
                        }
                    }
                }
            }
            if (w == 1 && tau < NTB) {
                int need = SPT * (tau + 3); if (need > T_) need = T_;
                while (*(volatile int*)&prog < need) __nanosleep(100);
                if (lane < 24) {
                    #pragma unroll
                    for (int s = 0; s < SPT; s++) {
                        xgbuf[rs][s][lane]      = HFC * rx[s];
                        xgbuf[rs][s][24 + lane] = HFC * rz_[s];
                        xgbuf[rs][s][48 + lane] = rn_[s];
                    }
                    #pragma unroll
                    for (int s = 0; s < SPT; s++) {
                        int st = SPT * tau + 2 * SPT + s;
                        if (st > T_ - 1) st = T_ - 1;
                        rx[s]  = xgp[(size_t)st * 72 + lane];
                        rz_[s] = xgp[(size_t)st * 72 + 24 + lane];
                        rn_[s] = xgp[(size_t)st * 72 + 48 + lane];
                    }
                }
            }
        }
        BAR_SYNC(2, 128);
    }

    if (write_extra && lane < 24) {
        if (w == 0) out_h1[b * 24 + lane] = hreg;   // h1(T-1)
        if (w == 2) out_h2[b * 24 + lane] = hreg;   // h2(T-1)
    }
}

// ---------------------------------------------------------------------------
extern "C" void kernel_launch(void* const* d_in, const int* in_sizes, int n_in,
                              void* d_out, int out_size)
{
    const float* x      = (const float*)d_in[0];
    const float* h1     = (const float*)d_in[1];
    const float* h2     = (const float*)d_in[2];
    const float* conv_w = (const float*)d_in[3];
    const float* conv_b = (const float*)d_in[4];
    const float* gamma  = (const float*)d_in[5];
    const float* beta   = (const float*)d_in[6];
    const float* w_ih1  = (const float*)d_in[7];
    const float* w_hh1  = (const float*)d_in[8];
    const float* b_ih1  = (const float*)d_in[9];
    const float* b_hh1  = (const float*)d_in[10];
    const float* w_ih2  = (const float*)d_in[11];
    const float* w_hh2  = (const float*)d_in[12];
    const float* b_ih2  = (const float*)d_in[13];
    const float* b_hh2  = (const float*)d_in[14];
    const float* fc_w   = (const float*)d_in[15];
    const float* fc_b   = (const float*)d_in[16];

    float* out = (float*)d_out;
    const size_t NOISE = (size_t)B_ * T_ * 32;
    const size_t FULL  = NOISE + 2 * (size_t)B_ * HID_ + (size_t)B_ * T_;
    int extra = ((size_t)out_size >= FULL) ? 1 : 0;
    float* o_h1   = out + NOISE;
    float* o_h2   = o_h1 + B_ * HID_;
    float* o_conf = o_h2 + B_ * HID_;

    const int PSMEM = (130 * 68 + 3072 + 64 * 3 + 4608 + 72) * (int)sizeof(float); // 67,136 B
    cudaFuncSetAttribute(fused_kernel, cudaFuncAttributeMaxDynamicSharedMemorySize, PSMEM);

    fused_kernel<<<B_, 256, PSMEM>>>(x, h1, h2, conv_w, conv_b, gamma, beta,
                                     w_ih1, b_ih1, w_hh1, b_hh1,
                                     w_ih2, w_hh2, b_ih2, b_hh2,
                                     fc_w, fc_b, out, o_h1, o_h2, o_conf, extra);
}

// round 15
// speedup vs baseline: 1.2819x; 1.2819x over previous
#include <cuda_runtime.h>

#define B_    128
#define T_    4096
#define FEAT_ 64
#define HID_  24
#define G3_   72            // 3 * HID
#define SPT   4             // steps per tick
#define NTB   (T_ / SPT)    // 1024 compute ticks for warp 0
#define NTICK (NTB + 3)     // + pipeline drain

// Scratch for precomputed GRU1 input gates: [B, T, 72]  (~151 MB)
__device__ float g_xg1[(size_t)B_ * T_ * G3_];

// sigmoid(a) = 0.5 + 0.5*tanh(a/2): r,z weights/biases/x pre-scaled by 0.5.
#define HFC 0.5f

typedef unsigned long long u64;

// ---------------------------------------------------------------------------
// Packed f32x2 helpers (PTX 8.6, sm_100+)
// ---------------------------------------------------------------------------
#define FMA2(acc, a, b) \
    asm("fma.rn.f32x2 %0, %1, %2, %0;" : "+l"(acc) : "l"(a), "l"(b))
#define ADD2(d, a, b) \
    asm("add.rn.f32x2 %0, %1, %2;" : "=l"(d) : "l"(a), "l"(b))
#define MUL2(d, a, b) \
    asm("mul.rn.f32x2 %0, %1, %2;" : "=l"(d) : "l"(a), "l"(b))
#define BAR_SYNC(id, cnt) \
    asm volatile("bar.sync %0, %1;" :: "r"(id), "r"(cnt) : "memory")

__device__ __forceinline__ u64 pk2(float lo, float hi) {
    u64 r;
    asm("mov.b64 %0, {%1, %2};" : "=l"(r) : "f"(lo), "f"(hi));
    return r;
}
__device__ __forceinline__ float hsum2(u64 v) {
    float lo, hi;
    asm("mov.b64 {%0, %1}, %2;" : "=f"(lo), "=f"(hi) : "l"(v));
    return lo + hi;
}
__device__ __forceinline__ float tanha(float x) {
    float r;
    asm("tanh.approx.f32 %0, %1;" : "=f"(r) : "f"(x));
    return r;
}
__device__ __forceinline__ void load_h64(u64 h64[12], const float* buf) {
    const ulonglong2* hp = (const ulonglong2*)buf;
    #pragma unroll
    for (int q = 0; q < 6; q++) { ulonglong2 v = hp[q]; h64[2*q] = v.x; h64[2*q+1] = v.y; }
}

// one GRU step: register h, shuffle-gathered pairs, MUFU-tanh gates.
__device__ __forceinline__ float gru_step_sh(float h,
    float xr_s, float xz_s, float xn,
    const u64* wr, const u64* wz, const u64* wn,
    float bhr_s, float bhz_s, float bhn)
{
    u64 h64[12];
    #pragma unroll
    for (int j = 0; j < 12; j++) {
        float lo = __shfl_sync(0xffffffffu, h, 2*j);
        float hi = __shfl_sync(0xffffffffu, h, 2*j+1);
        h64[j] = pk2(lo, hi);
    }
    u64 ar0 = pk2(xr_s, bhr_s), ar1 = 0ull;
    u64 az0 = pk2(xz_s, bhz_s), az1 = 0ull;
    u64 an0 = pk2(bhn, 0.f),    an1 = 0ull;
    #pragma unroll
    for (int j = 0; j < 6; j++) {
        FMA2(ar0, wr[j],     h64[j]);
        FMA2(ar1, wr[j + 6], h64[j + 6]);
        FMA2(an0, wn[j],     h64[j]);
        FMA2(an1, wn[j + 6], h64[j + 6]);
        FMA2(az0, wz[j],     h64[j]);
        FMA2(az1, wz[j + 6], h64[j + 6]);
    }
    ADD2(ar0, ar0, ar1);
    ADD2(an0, an0, an1);
    ADD2(az0, az0, az1);
    float r = fmaf(HFC, tanha(hsum2(ar0)), HFC);
    float n = tanha(fmaf(r, hsum2(an0), xn));
    float z = fmaf(HFC, tanha(hsum2(az0)), HFC);
    return fmaf(z, h - n, n);
}

// ---------------------------------------------------------------------------
// FUSED kernel (exact R13 configuration — best known): one CTA per batch,
// 8 warps. Warps 0-3: layer-pipelined GRU stack (barrier 2). Warps 4-7:
// conv+LN+xg1 producer (barrier 1) + smem progress counter.
// ---------------------------------------------------------------------------
__global__ void __launch_bounds__(256, 1) fused_kernel(
    const float* __restrict__ x,
    const float* __restrict__ h1_0, const float* __restrict__ h2_0,
    const float* __restrict__ conv_w, const float* __restrict__ conv_b,
    const float* __restrict__ gamma,  const float* __restrict__ beta,
    const float* __restrict__ w_ih1,  const float* __restrict__ b_ih1,
    const float* __restrict__ w_hh1, const float* __restrict__ b_hh1,
    const float* __restrict__ w_ih2, const float* __restrict__ w_hh2,
    const float* __restrict__ b_ih2, const float* __restrict__ b_hh2,
    const float* __restrict__ fc_w,  const float* __restrict__ fc_b,
    float* __restrict__ out_noise, float* __restrict__ out_h1,
    float* __restrict__ out_h2, int write_extra)
{
    // ---- producer dynamic smem ----
    extern __shared__ float psm[];
    float* xs  = psm;                // 130*68 = 8840
    float* cwt = xs + 130 * 68;      // 3072 (transposed [f][k][c])
    float* cb  = cwt + 3072;         // 64
    float* gm  = cb + 64;            // 64
    float* bt  = gm + 64;            // 64
    float* wi  = bt + 64;            // 4608
    float* b1  = wi + 4608;          // 72

    // ---- consumer static smem ----
    __shared__ __align__(16) float h1pub[2][SPT][24];
    __shared__ __align__(16) float h2pub[2][SPT][24];
    __shared__ __align__(16) float xg2buf[2][SPT][72];
    __shared__ __align__(16) float xgbuf[2][SPT][72];
    __shared__ int prog;

    const int b    = blockIdx.x;
    const int tid  = threadIdx.x;
    const int w    = tid >> 5;
    const int lane = tid & 31;

    if (tid == 0) prog = 0;
    __syncthreads();

    if (w >= 4) {
        // ================= PRODUCER (warps 4-7) =================
        const int ptid = tid - 128;
        for (int i = ptid; i < 3072; i += 128) {
            int f = i / 48, r = i % 48, k = r >> 4, c = r & 15;
            cwt[i] = conv_w[f * 48 + c * 3 + k];
        }
        for (int i = ptid; i < 4608; i += 128) wi[i] = w_ih1[i];
        if (ptid < 64) { cb[ptid] = conv_b[ptid]; gm[ptid] = gamma[ptid]; bt[ptid] = beta[ptid]; }
        if (ptid < 72) b1[ptid] = b_ih1[ptid];

        const float* xb = x + (size_t)b * T_ * FEAT_;
        for (int pass = 0; pass < T_ / 128; pass++) {
            const int t0 = pass << 7;
            for (int i = ptid; i < 130 * 64; i += 128) {
                int r = i >> 6, f = i & 63;
                int t = t0 - 2 + r;
                xs[r * 68 + f] = (t >= 0) ? xb[(size_t)t * 64 + f] : 0.f;
            }
            BAR_SYNC(1, 128);

            float y[64];
            #pragma unroll
            for (int g = 0; g < 4; g++) {
                u64 xk2[3][8];
                #pragma unroll
                for (int k = 0; k < 3; k++) {
                    const float4* p = (const float4*)&xs[(ptid + k) * 68 + g * 16];
                    #pragma unroll
                    for (int q = 0; q < 4; q++) {
                        float4 v = p[q];
                        xk2[k][2*q]   = pk2(v.x, v.y);
                        xk2[k][2*q+1] = pk2(v.z, v.w);
                    }
                }
                #pragma unroll
                for (int fo = 0; fo < 16; fo++) {
                    const int f = g * 16 + fo;
                    u64 a0 = 0ull, a1 = 0ull;
                    const ulonglong2* wp = (const ulonglong2*)&cwt[f * 48];
                    #pragma unroll
                    for (int k = 0; k < 3; k++) {
                        #pragma unroll
                        for (int q = 0; q < 4; q++) {
                            ulonglong2 wv = wp[k * 4 + q];
                            FMA2(a0, wv.x, xk2[k][2*q]);
                            FMA2(a1, wv.y, xk2[k][2*q+1]);
                        }
                    }
                    ADD2(a0, a0, a1);
                    y[f] = hsum2(a0) + cb[f];
                }
            }

            float s = 0.f, s2 = 0.f;
            #pragma unroll
            for (int f = 0; f < 64; f++) { s += y[f]; s2 = fmaf(y[f], y[f], s2); }
            float mean = s * (1.f / 64.f);
            float var  = s2 * (1.f / 64.f) - mean * mean;
            float rs   = rsqrtf(var + 1e-5f);
            #pragma unroll
            for (int f = 0; f < 64; f++) y[f] = (y[f] - mean) * rs * gm[f] + bt[f];

            u64 y2[32];
            #pragma unroll
            for (int j = 0; j < 32; j++) y2[j] = pk2(y[2*j], y[2*j+1]);

            float* outp = g_xg1 + ((size_t)b * T_ + (t0 + ptid)) * G3_;
            for (int o4 = 0; o4 < 18; o4++) {
                const int o = o4 * 4;
                u64 a0 = 0ull, a1 = 0ull, e0 = 0ull, e1 = 0ull;
                u64 c0 = 0ull, c1 = 0ull, d0 = 0ull, d1 = 0ull;
                const ulonglong2* w0 = (const ulonglong2*)&wi[(o + 0) * 64];
                const ulonglong2* w1 = (const ulonglong2*)&wi[(o + 1) * 64];
                const ulonglong2* w2 = (const ulonglong2*)&wi[(o + 2) * 64];
                const ulonglong2* w3 = (const ulonglong2*)&wi[(o + 3) * 64];
                #pragma unroll
                for (int c = 0; c < 16; c++) {
                    ulonglong2 v0 = w0[c], v1 = w1[c], v2 = w2[c], v3 = w3[c];
                    FMA2(a0, v0.x, y2[2*c]); FMA2(a1, v0.y, y2[2*c+1]);
                    FMA2(e0, v1.x, y2[2*c]); FMA2(e1, v1.y, y2[2*c+1]);
                    FMA2(c0, v2.x, y2[2*c]); FMA2(d0, v3.x, y2[2*c]);
                    FMA2(c1, v2.y, y2[2*c+1]); FMA2(d1, v3.y, y2[2*c+1]);
                }
                ADD2(a0, a0, a1); ADD2(e0, e0, e1); ADD2(c0, c0, c1); ADD2(d0, d0, d1);
                float4 res;
                res.x = hsum2(a0) + b1[o + 0];
                res.y = hsum2(e0) + b1[o + 1];
                res.z = hsum2(c0) + b1[o + 2];
                res.w = hsum2(d0) + b1[o + 3];
                ((float4*)outp)[o4] = res;
            }

            __threadfence_block();
            BAR_SYNC(1, 128);
            if (ptid == 0) *(volatile int*)&prog = (pass + 1) * 128;
        }
        return;
    }

    // ================= CONSUMER (warps 0-3) =================
    const int ln = (lane < 24) ? lane : (lane - 8);

    u64 wr[12], wz[12], wn[12], wf[12];
    float bhr = 0.f, bhz = 0.f, bhn = 0.f, bf = 0.f;
    {
        const u64 sH = pk2(HFC, HFC);
        const float* W  = (w == 0) ? w_hh1 : (w == 2) ? w_hh2 : w_ih2;
        const float* Bv = (w == 0) ? b_hh1 : (w == 2) ? b_hh2 : b_ih2;
        const u64* Wr = (const u64*)(W + ln * 24);
        const u64* Wz = (const u64*)(W + (24 + ln) * 24);
        const u64* Wn = (const u64*)(W + (48 + ln) * 24);
        #pragma unroll
        for (int j = 0; j < 12; j++) {
            u64 a = Wr[j], c = Wz[j];
            MUL2(wr[j], a, sH);
            MUL2(wz[j], c, sH);
            wn[j] = Wn[j];
        }
        bhr = HFC * Bv[ln]; bhz = HFC * Bv[24 + ln]; bhn = Bv[48 + ln];
        if (w == 1 || w == 3) {
            const u64* Wf = (const u64*)(fc_w + lane * 24);
            #pragma unroll
            for (int j = 0; j < 12; j++) wf[j] = Wf[j];
            bf = fc_b[lane];
        }
    }

    float hreg = 0.f;
    if (w == 0 && lane < 24) hreg = h1_0[b * 24 + lane];
    if (w == 2 && lane < 24) hreg = h2_0[b * 24 + lane];

    float* xgp = g_xg1 + (size_t)b * T_ * G3_;

    while (*(volatile int*)&prog < 8) __nanosleep(200);
    __threadfence_block();
    for (int i = tid; i < SPT * 72; i += 128) {
        int g = (i % 72) / 24;
        float sc = (g == 2) ? 1.f : HFC;
        ((float*)xgbuf[0])[i] = sc * xgp[i];
    }
    float rx[SPT], rz_[SPT], rn_[SPT];
    if (w == 1 && lane < 24) {
        #pragma unroll
        for (int s = 0; s < SPT; s++) {
            rx[s]  = xgp[(size_t)(SPT + s) * 72 + lane];
            rz_[s] = xgp[(size_t)(SPT + s) * 72 + 24 + lane];
            rn_[s] = xgp[(size_t)(SPT + s) * 72 + 48 + lane];
        }
    }
    BAR_SYNC(2, 128);

    for (int tau = 0; tau < NTICK; tau++) {
        const int ws = tau & 1, rs = ws ^ 1;
        if (w == 0) {
            if (tau < NTB) {
                float xr[SPT], xz[SPT], xn[SPT], hs[SPT];
                #pragma unroll
                for (int s = 0; s < SPT; s++) {
                    xr[s] = xgbuf[ws][s][ln];
                    xz[s] = xgbuf[ws][s][24 + ln];
                    xn[s] = xgbuf[ws][s][48 + ln];
                }
                #pragma unroll
                for (int s = 0; s < SPT; s++) {
                    hreg = gru_step_sh(hreg, xr[s], xz[s], xn[s],
                                       wr, wz, wn, bhr, bhz, bhn);
                    hs[s] = hreg;
                }
                if (lane < 24) {
                    #pragma unroll
                    for (int s = 0; s < SPT; s++) h1pub[ws][s][lane] = hs[s];
                }
            }
        } else if (w == 2) {
            if (tau >= 2 && tau <= NTB + 1) {
                float xr[SPT], xz[SPT], xn[SPT], hs[SPT];
                #pragma unroll
                for (int s = 0; s < SPT; s++) {
                    xr[s] = xg2buf[rs][s][ln];
                    xz[s] = xg2buf[rs][s][24 + ln];
                    xn[s] = xg2buf[rs][s][48 + ln];
                }
                #pragma unroll
                for (int s = 0; s < SPT; s++) {
                    hreg = gru_step_sh(hreg, xr[s], xz[s], xn[s],
                                       wr, wz, wn, bhr, bhz, bhn);
                    hs[s] = hreg;
                }
                if (lane < 24) {
                    #pragma unroll
                    for (int s = 0; s < SPT; s++) h2pub[ws][s][lane] = hs[s];
                }
            }
        } else {
            const int s0 = (w == 1) ? 0 : 2;
            if (tau >= 1 && tau <= NTB) {
                #pragma unroll
                for (int sel = 0; sel < 2; sel++) {
                    const int s = s0 + sel;
                    u64 h64[12];
                    load_h64(h64, h1pub[rs][s]);
                    u64 ar = pk2(bhr, 0.f);
                    u64 az = pk2(bhz, 0.f);
                    u64 an = pk2(bhn, 0.f);
                    #pragma unroll
                    for (int j = 0; j < 12; j++) {
                        FMA2(ar, wr[j], h64[j]); FMA2(az, wz[j], h64[j]); FMA2(an, wn[j], h64[j]);
                    }
                    if (lane < 24) {
                        xg2buf[ws][s][lane]      = hsum2(ar);
                        xg2buf[ws][s][24 + lane] = hsum2(az);
                        xg2buf[ws][s][48 + lane] = hsum2(an);
                    }
                }
            }
            if (tau >= 3) {
                const size_t t0o = (size_t)b * T_ + SPT * (tau - 3);
                #pragma unroll
                for (int sel = 0; sel < 2; sel++) {
                    const int s = s0 + sel;
                    u64 h64[12];
                    load_h64(h64, h2pub[rs][s]);
                    u64 a = pk2(bf, 0.f);
                    #pragma unroll
                    for (int j = 0; j < 12; j++) FMA2(a, wf[j], h64[j]);
                    out_noise[(t0o + s) * 32 + lane] = hsum2(a);
                }
            }
            if (w == 1 && tau < NTB) {
                int need = SPT * (tau + 3); if (need > T_) need = T_;
                while (*(volatile int*)&prog < need) __nanosleep(100);
                if (lane < 24) {
                    #pragma unroll
                    for (int s = 0; s < SPT; s++) {
                        xgbuf[rs][s][lane]      = HFC * rx[s];
                        xgbuf[rs][s][24 + lane] = HFC * rz_[s];
                        xgbuf[rs][s][48 + lane] = rn_[s];
                    }
                    #pragma unroll
                    for (int s = 0; s < SPT; s++) {
                        int st = SPT * tau + 2 * SPT + s;
                        if (st > T_ - 1) st = T_ - 1;
                        rx[s]  = xgp[(size_t)st * 72 + lane];
                        rz_[s] = xgp[(size_t)st * 72 + 24 + lane];
                        rn_[s] = xgp[(size_t)st * 72 + 48 + lane];
                    }
                }
            }
        }
        BAR_SYNC(2, 128);
    }

    if (write_extra && lane < 24) {
        if (w == 0) out_h1[b * 24 + lane] = hreg;   // h1(T-1)
        if (w == 2) out_h2[b * 24 + lane] = hreg;   // h2(T-1)
    }
}

// ---------------------------------------------------------------------------
// confidence = 1/(1+std(noise, ddof=1)) over last dim (32).
// ONE THREAD PER ROW: 8 independent float4 loads (MLP=8), zero shuffles.
// Each 128B line is fully consumed across the warp's 8 iterations via L1.
// ---------------------------------------------------------------------------
__global__ void __launch_bounds__(256) conf_kernel(
    const float* __restrict__ noise, float* __restrict__ conf)
{
    const size_t row = (size_t)blockIdx.x * 256 + threadIdx.x;
    const float4* p = (const float4*)(noise + row * 32);
    float4 v[8];
    #pragma unroll
    for (int i = 0; i < 8; i++) v[i] = p[i];

    float s0 = 0.f, s1 = 0.f, q0 = 0.f, q1 = 0.f;
    #pragma unroll
    for (int i = 0; i < 8; i += 2) {
        float4 a = v[i], c = v[i + 1];
        s0 += (a.x + a.y) + (a.z + a.w);
        s1 += (c.x + c.y) + (c.z + c.w);
        q0 = fmaf(a.x, a.x, q0); q0 = fmaf(a.y, a.y, q0);
        q0 = fmaf(a.z, a.z, q0); q0 = fmaf(a.w, a.w, q0);
        q1 = fmaf(c.x, c.x, q1); q1 = fmaf(c.y, c.y, q1);
        q1 = fmaf(c.z, c.z, q1); q1 = fmaf(c.w, c.w, q1);
    }
    float su = s0 + s1, sq = q0 + q1;
    float ss = fmaxf(sq - su * su * (1.f / 32.f), 0.f);
    float sd = sqrtf(ss * (1.f / 31.f));   // ddof = 1
    conf[row] = __fdividef(1.f, 1.f + sd);
}

// ---------------------------------------------------------------------------
extern "C" void kernel_launch(void* const* d_in, const int* in_sizes, int n_in,
                              void* d_out, int out_size)
{
    const float* x      = (const float*)d_in[0];
    const float* h1     = (const float*)d_in[1];
    const float* h2     = (const float*)d_in[2];
    const float* conv_w = (const float*)d_in[3];
    const float* conv_b = (const float*)d_in[4];
    const float* gamma  = (const float*)d_in[5];
    const float* beta   = (const float*)d_in[6];
    const float* w_ih1  = (const float*)d_in[7];
    const float* w_hh1  = (const float*)d_in[8];
    const float* b_ih1  = (const float*)d_in[9];
    const float* b_hh1  = (const float*)d_in[10];
    const float* w_ih2  = (const float*)d_in[11];
    const float* w_hh2  = (const float*)d_in[12];
    const float* b_ih2  = (const float*)d_in[13];
    const float* b_hh2  = (const float*)d_in[14];
    const float* fc_w   = (const float*)d_in[15];
    const float* fc_b   = (const float*)d_in[16];

    float* out = (float*)d_out;
    const size_t NOISE = (size_t)B_ * T_ * 32;
    const size_t FULL  = NOISE + 2 * (size_t)B_ * HID_ + (size_t)B_ * T_;
    int extra = ((size_t)out_size >= FULL) ? 1 : 0;
    float* o_h1   = out + NOISE;
    float* o_h2   = o_h1 + B_ * HID_;
    float* o_conf = o_h2 + B_ * HID_;

    const int PSMEM = (130 * 68 + 3072 + 64 * 3 + 4608 + 72) * (int)sizeof(float); // 67,136 B
    cudaFuncSetAttribute(fused_kernel, cudaFuncAttributeMaxDynamicSharedMemorySize, PSMEM);

    fused_kernel<<<B_, 256, PSMEM>>>(x, h1, h2, conv_w, conv_b, gamma, beta,
                                     w_ih1, b_ih1, w_hh1, b_hh1,
                                     w_ih2, w_hh2, b_ih2, b_hh2,
                                     fc_w, fc_b, out, o_h1, o_h2, extra);
    if (extra) conf_kernel<<<(B_ * T_) / 256, 256>>>(out, o_conf);
}